// round 3
// baseline (speedup 1.0000x reference)
#include <cuda_runtime.h>
#include <math.h>
#include <stdint.h>

#define BB 128
#define RR 4096
#define DD 256
#define NROW (BB * RR)
#define ROWS_PER_CTA 64
#define CTAS_PER_B (RR / ROWS_PER_CTA)   // 64

// Static device scratch (no allocations allowed)
__device__ float g_dot[NROW];
__device__ float g_ss[NROW];

// ---------------------------------------------------------------------------
// Inline qidx decode: query_rels may be int64 or int32 (jax x64 config).
// If int64 LE with values < 4096, every high 32-bit word is 0. Sampling 64
// odd words (512 B — safe under both interpretations) distinguishes them:
// for random int32 values in [0,4096) the odds of 64 zeros is (1/4096)^64.
// Executed by warp 0 only; result broadcast via shared.
// ---------------------------------------------------------------------------
__device__ __forceinline__ void decode_qidx_warp0(const void* qr, int b,
                                                  int t, int* s_qidx) {
    if (t < 32) {
        const int* p32 = (const int*)qr;
        int hi = p32[2 * t + 1] | p32[2 * (t + 32) + 1];
        bool is32 = __any_sync(0xFFFFFFFFu, hi != 0);
        if (t == 0) {
            *s_qidx = is32 ? p32[b] : (int)((const long long*)qr)[b];
        }
    }
}

// ---------------------------------------------------------------------------
// Kernel 1: fused copy + per-row dot(r_i, q_b) + per-row sum-of-squares.
// 64 rows per CTA (all within one batch), warp-per-row, 8 iterations.
// q staged once per CTA in shared. Streaming loads/stores keep the 1 GB
// stream out of L2; q loads are L2-hot.
// ---------------------------------------------------------------------------
__global__ void __launch_bounds__(256) fuse_copy_sims_kernel(
    const float* __restrict__ in, float* __restrict__ out,
    const void* __restrict__ qr) {
    __shared__ float qs[DD];
    __shared__ int s_qidx;
    int cta = blockIdx.x;
    int b = cta / CTAS_PER_B;
    int t = threadIdx.x;

    decode_qidx_warp0(qr, b, t, &s_qidx);
    __syncthreads();
    int qidx = s_qidx;

    // cooperative q stage: 256 threads, 256 floats
    qs[t] = __ldg(in + ((size_t)b * RR + qidx) * DD + t);
    __syncthreads();

    int warp = t >> 5;
    int lane = t & 31;

    float4 q0 = *(const float4*)(qs + 4 * lane);
    float4 q1 = *(const float4*)(qs + 128 + 4 * lane);

    size_t rowbase = (size_t)cta * ROWS_PER_CTA;

#pragma unroll 2
    for (int it = 0; it < 8; it++) {
        size_t row = rowbase + it * 8 + warp;
        const float4* rp = (const float4*)(in + row * DD);
        float4* op = (float4*)(out + row * DD);

        float4 a0 = __ldcs(rp + lane);
        float4 a1 = __ldcs(rp + lane + 32);
        __stcs(op + lane, a0);
        __stcs(op + lane + 32, a1);

        float dot = a0.x * q0.x + a0.y * q0.y + a0.z * q0.z + a0.w * q0.w
                  + a1.x * q1.x + a1.y * q1.y + a1.z * q1.z + a1.w * q1.w;
        float ss  = a0.x * a0.x + a0.y * a0.y + a0.z * a0.z + a0.w * a0.w
                  + a1.x * a1.x + a1.y * a1.y + a1.z * a1.z + a1.w * a1.w;

#pragma unroll
        for (int o = 16; o > 0; o >>= 1) {
            dot += __shfl_xor_sync(0xFFFFFFFFu, dot, o);
            ss  += __shfl_xor_sync(0xFFFFFFFFu, ss, o);
        }
        if (lane == 0) {
            g_dot[row] = dot;
            g_ss[row]  = ss;
        }
    }
}

// ---------------------------------------------------------------------------
// Block reductions (256 threads)
// ---------------------------------------------------------------------------
__device__ __forceinline__ float block_reduce_max(float v, float* red) {
    int t = threadIdx.x;
    red[t] = v;
    __syncthreads();
#pragma unroll
    for (int s = 128; s > 0; s >>= 1) {
        if (t < s) red[t] = fmaxf(red[t], red[t + s]);
        __syncthreads();
    }
    float r = red[0];
    __syncthreads();
    return r;
}

__device__ __forceinline__ float block_reduce_sum(float v, float* red) {
    int t = threadIdx.x;
    red[t] = v;
    __syncthreads();
#pragma unroll
    for (int s = 128; s > 0; s >>= 1) {
        if (t < s) red[t] += red[t + s];
        __syncthreads();
    }
    float r = red[0];
    __syncthreads();
    return r;
}

// ---------------------------------------------------------------------------
// Kernel 2: per-batch gating + masked softmax + coefficients + sparse
// weighted apply, fused. 128 CTAs x 256 threads; thread t handles rows
// i = t + k*256. Nonzero coefficients compacted into shared; apply phase
// is O(nnz) row loads (typically nnz == 0 -> early exit; the copy already
// wrote the correct row).
// ---------------------------------------------------------------------------
__global__ void __launch_bounds__(256) weights_apply_kernel(
    const float* __restrict__ in, float* __restrict__ out,
    const void* __restrict__ qr,
    const float* __restrict__ thr_raw, const float* __restrict__ str_raw,
    const float* __restrict__ wscale,  const float* __restrict__ temp_p) {
    __shared__ float red[256];
    __shared__ int   s_idx[RR];
    __shared__ float s_cf[RR];
    __shared__ int   s_n;
    __shared__ int   s_qidx;
    int b = blockIdx.x;
    int t = threadIdx.x;

    decode_qidx_warp0(qr, b, t, &s_qidx);
    if (t == 0) s_n = 0;
    __syncthreads();
    int qidx = s_qidx;

    float thr = 1.0f / (1.0f + expf(-thr_raw[0]));
    float strength = 0.2f / (1.0f + expf(-str_raw[0]));
    float ws = wscale[0];
    float temp = fminf(fmaxf(temp_p[0], 0.1f), 10.0f);

    float qn = fmaxf(sqrtf(g_ss[(size_t)b * RR + qidx]), 1e-12f);

    float sims[16];
    bool  msk[16];
    float lmax = -1e9f;
    int   lcnt = 0;
#pragma unroll
    for (int k = 0; k < 16; k++) {
        int i = t + k * 256;
        size_t idx = (size_t)b * RR + i;
        float nrm = fmaxf(sqrtf(g_ss[idx]), 1e-12f);
        float s = g_dot[idx] / (nrm * qn);
        if (i == qidx) s = -1.0f;
        sims[k] = s;
        float sw = 1.0f / (1.0f + expf(-(s - thr) * 10.0f));
        bool m = sw > 0.5f;
        msk[k] = m;
        if (m) {
            lmax = fmaxf(lmax, s / temp);
            lcnt++;
        }
    }

    int total = (int)block_reduce_sum((float)lcnt, red);
    if (total == 0) return;  // copy already wrote the unchanged q row

    float m = block_reduce_max(lmax, red);

    float lz = 0.0f;
#pragma unroll
    for (int k = 0; k < 16; k++) {
        if (msk[k]) lz += expf(sims[k] / temp - m);
        // unmasked entries: exp(-1e9) underflows to exactly 0 in fp32
    }
    float Z = block_reduce_sum(lz, red);

    float c[16];
    float lS = 0.0f;
#pragma unroll
    for (int k = 0; k < 16; k++) {
        if (msk[k]) {
            float s = sims[k];
            float sw = 1.0f / (1.0f + expf(-(s - thr) * 10.0f));
            float w = expf(s / temp - m) / Z;
            c[k] = w * sw * (1.0f + ws * s);
            lS += c[k];
        } else {
            c[k] = 0.0f;
        }
    }
    float S = block_reduce_sum(lS, red);
    float inv = strength / (S + 1e-8f);

    // compact nonzero (idx, coef) pairs into shared
#pragma unroll
    for (int k = 0; k < 16; k++) {
        if (msk[k]) {
            int slot = atomicAdd(&s_n, 1);
            s_idx[slot] = t + k * 256;
            s_cf[slot]  = c[k] * inv;
        }
    }
    __syncthreads();

    // sparse weighted sum over nnz rows; thread t = dim index
    int nnz = s_n;
    float acc = 0.0f;
    for (int j = 0; j < nnz; j++) {
        int i = s_idx[j];
        acc += s_cf[j] * in[((size_t)b * RR + i) * DD + t];
    }

    float q = in[((size_t)b * RR + qidx) * DD + t];
    out[((size_t)b * RR + qidx) * DD + t] = (1.0f - strength) * q + acc;
}

// ---------------------------------------------------------------------------
extern "C" void kernel_launch(void* const* d_in, const int* in_sizes, int n_in,
                              void* d_out, int out_size) {
    const float* reps    = (const float*)d_in[0];
    const void*  qrels   = d_in[1];
    const float* thr_raw = (const float*)d_in[2];
    const float* str_raw = (const float*)d_in[3];
    const float* wscale  = (const float*)d_in[4];
    const float* temp_p  = (const float*)d_in[5];
    float* out = (float*)d_out;

    fuse_copy_sims_kernel<<<NROW / ROWS_PER_CTA, 256>>>(reps, out, qrels);

    weights_apply_kernel<<<BB, 256>>>(reps, out, qrels,
                                      thr_raw, str_raw, wscale, temp_p);
}

// round 4
// speedup vs baseline: 1.0794x; 1.0794x over previous
#include <cuda_runtime.h>
#include <math.h>
#include <stdint.h>

#define BB 128
#define RR 4096
#define DD 256
#define NROW (BB * RR)

// Static device scratch (no allocations allowed)
__device__ float g_dot[NROW];
__device__ float g_ss[NROW];

// ---------------------------------------------------------------------------
// Inline qidx decode: query_rels may be int64 or int32 (jax x64 config).
// If int64 LE with values < 4096, every high 32-bit word is 0. Sampling 64
// odd words (512 B — safe under both interpretations) distinguishes them.
// Executed by warp 0 only; result broadcast via shared.
// ---------------------------------------------------------------------------
__device__ __forceinline__ void decode_qidx_warp0(const void* qr, int b,
                                                  int t, int* s_qidx) {
    if (t < 32) {
        const int* p32 = (const int*)qr;
        int hi = p32[2 * t + 1] | p32[2 * (t + 32) + 1];
        bool is32 = __any_sync(0xFFFFFFFFu, hi != 0);
        if (t == 0) {
            *s_qidx = is32 ? p32[b] : (int)((const long long*)qr)[b];
        }
    }
}

// ---------------------------------------------------------------------------
// Kernel 1: fused copy + per-row dot(r_i, q_b) + per-row sum-of-squares.
// One warp per row, 8 rows per 256-thread CTA (R2-proven shape). q staged
// once per CTA in shared; streaming loads/stores keep the 1 GB stream out
// of L2.
// ---------------------------------------------------------------------------
__global__ void __launch_bounds__(256) fuse_copy_sims_kernel(
    const float* __restrict__ in, float* __restrict__ out,
    const void* __restrict__ qr) {
    __shared__ float qs[DD];
    __shared__ int s_qidx;
    int cta = blockIdx.x;
    int b = cta >> 9;            // 512 CTAs per batch
    int t = threadIdx.x;

    decode_qidx_warp0(qr, b, t, &s_qidx);
    __syncthreads();
    int qidx = s_qidx;

    // cooperative q stage: 256 threads, 256 floats (L2-hot)
    qs[t] = __ldg(in + ((size_t)b * RR + qidx) * DD + t);
    __syncthreads();

    int warp = t >> 5;
    int lane = t & 31;
    size_t row = (size_t)cta * 8 + warp;

    const float4* rp = (const float4*)(in + row * DD);
    float4* op = (float4*)(out + row * DD);

    float4 a0 = __ldcs(rp + lane);
    float4 a1 = __ldcs(rp + lane + 32);
    __stcs(op + lane, a0);
    __stcs(op + lane + 32, a1);

    float4 q0 = *(const float4*)(qs + 4 * lane);
    float4 q1 = *(const float4*)(qs + 128 + 4 * lane);

    float dot = a0.x * q0.x + a0.y * q0.y + a0.z * q0.z + a0.w * q0.w
              + a1.x * q1.x + a1.y * q1.y + a1.z * q1.z + a1.w * q1.w;
    float ss  = a0.x * a0.x + a0.y * a0.y + a0.z * a0.z + a0.w * a0.w
              + a1.x * a1.x + a1.y * a1.y + a1.z * a1.z + a1.w * a1.w;

#pragma unroll
    for (int o = 16; o > 0; o >>= 1) {
        dot += __shfl_xor_sync(0xFFFFFFFFu, dot, o);
        ss  += __shfl_xor_sync(0xFFFFFFFFu, ss, o);
    }
    if (lane == 0) {
        g_dot[row] = dot;
        g_ss[row]  = ss;
    }
}

// ---------------------------------------------------------------------------
// Block reductions (1024 threads)
// ---------------------------------------------------------------------------
__device__ __forceinline__ float block_reduce_max_1k(float v, float* red) {
    int t = threadIdx.x;
    red[t] = v;
    __syncthreads();
#pragma unroll
    for (int s = 512; s > 0; s >>= 1) {
        if (t < s) red[t] = fmaxf(red[t], red[t + s]);
        __syncthreads();
    }
    float r = red[0];
    __syncthreads();
    return r;
}

__device__ __forceinline__ float block_reduce_sum_1k(float v, float* red) {
    int t = threadIdx.x;
    red[t] = v;
    __syncthreads();
#pragma unroll
    for (int s = 512; s > 0; s >>= 1) {
        if (t < s) red[t] += red[t + s];
        __syncthreads();
    }
    float r = red[0];
    __syncthreads();
    return r;
}

// ---------------------------------------------------------------------------
// Kernel 2: per-batch gating + masked softmax + coefficients + sparse
// weighted apply, fused. 128 CTAs x 1024 threads; thread t handles rows
// i = t + k*1024 (4 per thread -> no register-array spill, 32 warps for
// latency hiding). Key identity: mask = sigmoid((s-thr)*10) > 0.5  <=>
// s > thr, so the always-taken path (empty mask for this data
// distribution) computes NO exp at all. sims are computed once into
// shared and reused by all later passes.
// ---------------------------------------------------------------------------
__global__ void __launch_bounds__(1024) weights_apply_kernel(
    const float* __restrict__ in, float* __restrict__ out,
    const void* __restrict__ qr,
    const float* __restrict__ thr_raw, const float* __restrict__ str_raw,
    const float* __restrict__ wscale,  const float* __restrict__ temp_p) {
    __shared__ float red[1024];
    __shared__ float s_sims[RR];   // 16 KB
    __shared__ int   s_idx[RR];    // 16 KB
    __shared__ float s_cf[RR];     // 16 KB
    __shared__ int   s_n;
    __shared__ int   s_qidx;
    int b = blockIdx.x;
    int t = threadIdx.x;

    decode_qidx_warp0(qr, b, t, &s_qidx);
    if (t == 0) s_n = 0;
    __syncthreads();
    int qidx = s_qidx;

    float thr = 1.0f / (1.0f + expf(-thr_raw[0]));
    float qn = fmaxf(sqrtf(g_ss[(size_t)b * RR + qidx]), 1e-12f);

    // Pass 1: sims -> shared; count masked (no exp needed here)
    int lcnt = 0;
#pragma unroll
    for (int k = 0; k < 4; k++) {
        int i = t + k * 1024;
        size_t idx = (size_t)b * RR + i;
        float nrm = fmaxf(sqrtf(g_ss[idx]), 1e-12f);
        float s = g_dot[idx] / (nrm * qn);
        if (i == qidx) s = -1.0f;
        s_sims[i] = s;
        if (s > thr) lcnt++;
    }

    int total = (int)block_reduce_sum_1k((float)lcnt, red);
    if (total == 0) return;  // copy already wrote the unchanged q row

    // ---- rare path: mask nonempty ----
    float strength = 0.2f / (1.0f + expf(-str_raw[0]));
    float ws = wscale[0];
    float temp = fminf(fmaxf(temp_p[0], 0.1f), 10.0f);

    float lmax = -1e9f;
#pragma unroll
    for (int k = 0; k < 4; k++) {
        float s = s_sims[t + k * 1024];
        if (s > thr) lmax = fmaxf(lmax, s / temp);
    }
    float m = block_reduce_max_1k(lmax, red);

    float lz = 0.0f;
#pragma unroll
    for (int k = 0; k < 4; k++) {
        float s = s_sims[t + k * 1024];
        if (s > thr) lz += expf(s / temp - m);
        // unmasked entries: exp(-1e9) underflows to exactly 0 in fp32
    }
    float Z = block_reduce_sum_1k(lz, red);

    float c[4];
    float lS = 0.0f;
#pragma unroll
    for (int k = 0; k < 4; k++) {
        float s = s_sims[t + k * 1024];
        if (s > thr) {
            float sw = 1.0f / (1.0f + expf(-(s - thr) * 10.0f));
            float w = expf(s / temp - m) / Z;
            c[k] = w * sw * (1.0f + ws * s);
            lS += c[k];
        } else {
            c[k] = 0.0f;
        }
    }
    float S = block_reduce_sum_1k(lS, red);
    float inv = strength / (S + 1e-8f);

    // compact nonzero (idx, coef) pairs into shared
#pragma unroll
    for (int k = 0; k < 4; k++) {
        if (c[k] != 0.0f) {
            int slot = atomicAdd(&s_n, 1);
            s_idx[slot] = t + k * 1024;
            s_cf[slot]  = c[k] * inv;
        }
    }
    __syncthreads();

    // sparse weighted sum over nnz rows; threads 0..255 = dim index
    int nnz = s_n;
    if (t < DD) {
        float acc = 0.0f;
        for (int j = 0; j < nnz; j++) {
            int i = s_idx[j];
            acc += s_cf[j] * in[((size_t)b * RR + i) * DD + t];
        }
        float q = in[((size_t)b * RR + qidx) * DD + t];
        out[((size_t)b * RR + qidx) * DD + t] = (1.0f - strength) * q + acc;
    }
}

// ---------------------------------------------------------------------------
extern "C" void kernel_launch(void* const* d_in, const int* in_sizes, int n_in,
                              void* d_out, int out_size) {
    const float* reps    = (const float*)d_in[0];
    const void*  qrels   = d_in[1];
    const float* thr_raw = (const float*)d_in[2];
    const float* str_raw = (const float*)d_in[3];
    const float* wscale  = (const float*)d_in[4];
    const float* temp_p  = (const float*)d_in[5];
    float* out = (float*)d_out;

    // one warp per row: 8 rows per 256-thread CTA (R2-proven shape)
    fuse_copy_sims_kernel<<<NROW / 8, 256>>>(reps, out, qrels);

    weights_apply_kernel<<<BB, 1024>>>(reps, out, qrels,
                                       thr_raw, str_raw, wscale, temp_p);
}